// round 7
// baseline (speedup 1.0000x reference)
#include <cuda_runtime.h>
#include <cstdint>

// Problem constants
constexpr int B_  = 32;
constexpr int T_  = 1024;
constexpr int F_  = 512;
constexpr int H_  = 512;
constexpr int G4H = 2048;   // 4*H

#define NB 128   // recurrence blocks; 16 producer blocks per k-slice
#define NT 256   // 8 warps: warp w owns k-slice [64w, 64w+64)
#define KW 64    // k per warp

// ---------------- device scratch ----------------
__device__ float g_z0t[(size_t)T_ * G4H * B_];   // [t][gatecol][b]
__device__ float g_hT[4][H_ * B_];               // 4-deep ring, transposed [k][b]
// Monotonic dataflow counters (reset by gemm block (0,0) each call).
__device__ unsigned g_hready[8 * 32];            // per-slice producer counters
__device__ unsigned g_sdone[4 * 32];             // per-ring-slot stage counters

// ---------------- f32x2 + sync helpers ----------------
__device__ __forceinline__ unsigned long long pack2(float x, float y) {
    unsigned long long r;
    asm("mov.b64 %0, {%1, %2};" : "=l"(r) : "f"(x), "f"(y));
    return r;
}
__device__ __forceinline__ unsigned long long fma2(unsigned long long a,
                                                   unsigned long long b,
                                                   unsigned long long c) {
    unsigned long long d;
    asm("fma.rn.f32x2 %0, %1, %2, %3;" : "=l"(d) : "l"(a), "l"(b), "l"(c));
    return d;
}
__device__ __forceinline__ unsigned long long add2(unsigned long long a,
                                                   unsigned long long b) {
    unsigned long long d;
    asm("add.rn.f32x2 %0, %1, %2;" : "=l"(d) : "l"(a), "l"(b));
    return d;
}
__device__ __forceinline__ float2 unpack2(unsigned long long v) {
    float2 f;
    asm("mov.b64 {%0, %1}, %2;" : "=f"(f.x), "=f"(f.y) : "l"(v));
    return f;
}
__device__ __forceinline__ unsigned ld_acq(const unsigned* p) {
    unsigned v;
    asm volatile("ld.acquire.gpu.global.u32 %0, [%1];"
                 : "=r"(v) : "l"(p) : "memory");
    return v;
}
__device__ __forceinline__ void red_rel_add1(unsigned* p) {
    asm volatile("red.release.gpu.global.add.u32 [%0], 1;"
                 :: "l"(p) : "memory");
}

// ---------------- GEMM (f32x2) + embedded init (validated) ----------------
__global__ void __launch_bounds__(256) gemm_xwi(const float* __restrict__ x,
                                                const float* __restrict__ Wi,
                                                const float* __restrict__ bias,
                                                const float* __restrict__ h0) {
    __shared__ float As[16][64];
    __shared__ float Bs[16][64];
    const int tid = threadIdx.x;

    if (blockIdx.x == 0 && blockIdx.y == 0) {
        for (int i = tid; i < H_ * B_; i += 256) {
            int b = i / H_;
            int k = i - b * H_;
            g_hT[0][k * B_ + b] = h0[i];
        }
        if (tid < 8 * 32) g_hready[tid] = 0;
        if (tid < 4 * 32) g_sdone[tid] = 0;
    }

    const int tm = tid >> 4;
    const int tn = tid & 15;
    const int row0 = blockIdx.y * 64;
    const int col0 = blockIdx.x * 64;

    unsigned long long acc[4][2] = {};

    const int ar  = tid >> 2;
    const int akq = (tid & 3) * 4;
    const int br  = tid >> 4;
    const int bnq = (tid & 15) * 4;

    for (int kt = 0; kt < F_; kt += 16) {
        float4 av = *(const float4*)&x[(size_t)(row0 + ar) * F_ + kt + akq];
        As[akq + 0][ar] = av.x;
        As[akq + 1][ar] = av.y;
        As[akq + 2][ar] = av.z;
        As[akq + 3][ar] = av.w;
        *(float4*)&Bs[br][bnq] =
            *(const float4*)&Wi[(size_t)(kt + br) * G4H + col0 + bnq];
        __syncthreads();
#pragma unroll
        for (int k = 0; k < 16; k++) {
            float4 a = *(const float4*)&As[k][tm * 4];
            const unsigned long long* bp =
                (const unsigned long long*)&Bs[k][tn * 4];
            unsigned long long b0 = bp[0], b1 = bp[1];
            unsigned long long a0 = pack2(a.x, a.x);
            unsigned long long a1 = pack2(a.y, a.y);
            unsigned long long a2 = pack2(a.z, a.z);
            unsigned long long a3 = pack2(a.w, a.w);
            acc[0][0] = fma2(a0, b0, acc[0][0]); acc[0][1] = fma2(a0, b1, acc[0][1]);
            acc[1][0] = fma2(a1, b0, acc[1][0]); acc[1][1] = fma2(a1, b1, acc[1][1]);
            acc[2][0] = fma2(a2, b0, acc[2][0]); acc[2][1] = fma2(a2, b1, acc[2][1]);
            acc[3][0] = fma2(a3, b0, acc[3][0]); acc[3][1] = fma2(a3, b1, acc[3][1]);
        }
        __syncthreads();
    }

#pragma unroll
    for (int i = 0; i < 4; i++) {
        int r  = row0 + tm * 4 + i;
        int t  = r & (T_ - 1);
        int bb = r >> 10;
#pragma unroll
        for (int j = 0; j < 2; j++) {
            float2 v = unpack2(acc[i][j]);
            int c0c = col0 + tn * 4 + j * 2;
            g_z0t[((size_t)t * G4H + c0c + 0) * B_ + bb] = v.x + bias[c0c + 0];
            g_z0t[((size_t)t * G4H + c0c + 1) * B_ + bb] = v.y + bias[c0c + 1];
        }
    }
}

// ---------------- recurrence: pipelined producer/consumer dataflow ----------------
// Block bx owns h columns [bx*4, bx*4+4) (slice bx>>4 of h).
// Warp w stages & consumes ONLY k-slice [64w,64w+64), gated by g_hready[w].
// Ring slot for h(t) is t&3; slot reuse protected by g_sdone (3-step slack).
__global__ void __launch_bounds__(NT, 1) lstm_rec(const float* __restrict__ c0,
                                                  const float* __restrict__ Wh,
                                                  float* __restrict__ out) {
    extern __shared__ unsigned char dsm[];
    unsigned long long* Wsu = (unsigned long long*)dsm;          // [k*8 + nl*2]
    float* hs = (float*)(Wsu + 512 * 8);                         // [k*32 + b]
    unsigned long long* red = (unsigned long long*)(hs + 512*32);// [j*256+w*32+b]
    float* hout = (float*)(red + 8 * 8 * 32);                    // [b*4 + nl]

    const int tid  = threadIdx.x;
    const int w    = tid >> 5;
    const int lane = tid & 31;
    const int b    = lane;
    const int myslice = blockIdx.x >> 4;         // slice this block produces into

    // Stage Wh slice once: (wi,wf),(wg,wo) pairs per (k, col nl).
    for (int idx = tid; idx < H_ * 4; idx += NT) {
        int k  = idx >> 2;
        int n2 = idx & 3;
        int cb = blockIdx.x * 4 + n2;
        float wi = Wh[(size_t)k * G4H + 0 * H_ + cb];
        float wf = Wh[(size_t)k * G4H + 1 * H_ + cb];
        float wg = Wh[(size_t)k * G4H + 2 * H_ + cb];
        float wo = Wh[(size_t)k * G4H + 3 * H_ + cb];
        Wsu[k * 8 + n2 * 2 + 0] = pack2(wi, wf);
        Wsu[k * 8 + n2 * 2 + 1] = pack2(wg, wo);
    }

    // Epilogue-mapped state (tid < 128): nl = tid>>5, bb = tid&31.
    const int nl = tid >> 5;
    const int bb = tid & 31;
    const int ncol = blockIdx.x * 4 + nl;
    float c = (tid < 128) ? c0[(size_t)bb * H_ + ncol] : 0.f;

    float* c_fin = out;
    float* h_fin = out + B_ * H_;
    float* hist  = out + 2 * B_ * H_;            // [b][t][h]

    __syncthreads();

    for (int t = 0; t < T_; t++) {
        const int sr = t & 3;
        const int sw = (t + 1) & 3;
        const float4* __restrict__ hsrc4 = (const float4*)g_hT[sr];
        float* hdst = g_hT[sw];
        float4* hsf4 = (float4*)hs;

        // ---- z prefetch (epilogue threads; independent of sync) ----
        float z0 = 0.f, z1 = 0.f, z2 = 0.f, z3 = 0.f;
        if (tid < 128) {
            size_t zb = ((size_t)t * G4H + ncol) * B_ + bb;
            z0 = __ldcs(&g_z0t[zb + (size_t)0 * H_ * B_]);
            z1 = __ldcs(&g_z0t[zb + (size_t)1 * H_ * B_]);
            z2 = __ldcs(&g_z0t[zb + (size_t)2 * H_ * B_]);
            z3 = __ldcs(&g_z0t[zb + (size_t)3 * H_ * B_]);
        }

        // ---- forward sync: wait for the 16 producers of THIS warp's slice ----
        if (t > 0 && lane == 0) {
            unsigned tgt = 16u * (unsigned)t;
            while (ld_acq(&g_hready[w * 32]) < tgt) { }
        }
        __syncwarp();

        // ---- warp-local stage: this warp's 8KB k-slice (512 float4/warp) ----
        {
            const int base = w * 512;
#pragma unroll
            for (int i = 0; i < 16; i += 4) {
                int j0 = base + (i + 0) * 32 + b;
                int j1 = base + (i + 1) * 32 + b;
                int j2 = base + (i + 2) * 32 + b;
                int j3 = base + (i + 3) * 32 + b;
                float4 r0 = __ldcg(&hsrc4[j0]);
                float4 r1 = __ldcg(&hsrc4[j1]);
                float4 r2 = __ldcg(&hsrc4[j2]);
                float4 r3 = __ldcg(&hsrc4[j3]);
                hsf4[j0] = r0; hsf4[j1] = r1; hsf4[j2] = r2; hsf4[j3] = r3;
            }
        }
        __syncwarp();

        // ---- compute: 64 k, 16 FMA2s each (4 cols x 4 gates) ----
        unsigned long long a0 = 0, a1 = 0, a2 = 0, a3 = 0;
        unsigned long long a4 = 0, a5 = 0, a6 = 0, a7 = 0;
        {
            const float* hp = hs + (size_t)w * KW * 32 + b;
            const ulonglong2* wp = (const ulonglong2*)(Wsu + (size_t)w * KW * 8);
#pragma unroll 4
            for (int kk = 0; kk < KW; kk++) {
                float hv = hp[kk * 32];
                unsigned long long hh = pack2(hv, hv);
                ulonglong2 w01 = wp[kk * 4 + 0];
                ulonglong2 w23 = wp[kk * 4 + 1];
                ulonglong2 w45 = wp[kk * 4 + 2];
                ulonglong2 w67 = wp[kk * 4 + 3];
                a0 = fma2(hh, w01.x, a0); a1 = fma2(hh, w01.y, a1);
                a2 = fma2(hh, w23.x, a2); a3 = fma2(hh, w23.y, a3);
                a4 = fma2(hh, w45.x, a4); a5 = fma2(hh, w45.y, a5);
                a6 = fma2(hh, w67.x, a6); a7 = fma2(hh, w67.y, a7);
            }
        }

        // ---- publish partials: red[j][w][b] (conflict-free) ----
        red[0 * 256 + w * 32 + b] = a0;
        red[1 * 256 + w * 32 + b] = a1;
        red[2 * 256 + w * 32 + b] = a2;
        red[3 * 256 + w * 32 + b] = a3;
        red[4 * 256 + w * 32 + b] = a4;
        red[5 * 256 + w * 32 + b] = a5;
        red[6 * 256 + w * 32 + b] = a6;
        red[7 * 256 + w * 32 + b] = a7;

        // ---- back-pressure: ring slot sw reusable? (3-step slack; off path) ----
        if (tid == 255) {
            unsigned need = 128u * ((unsigned)(t + 1) >> 2);
            if (need) {
                while (ld_acq(&g_sdone[sw * 32]) < need) { }
            }
        }
        __syncthreads();

        // ---- mark this block's staging of h(t) complete (slot sr) ----
        if (tid == 128) red_rel_add1(&g_sdone[sr * 32]);

        // ---- reduce + gates (epilogue threads, col nl / batch bb) ----
        if (tid < 128) {
            const unsigned long long* rif = red + (nl * 2 + 0) * 256 + bb;
            const unsigned long long* rgo = red + (nl * 2 + 1) * 256 + bb;
            unsigned long long aif = pack2(z0, z1);
            unsigned long long ago = pack2(z2, z3);
#pragma unroll
            for (int ww = 0; ww < 8; ww++) {
                aif = add2(aif, rif[ww * 32]);
                ago = add2(ago, rgo[ww * 32]);
            }
            float2 zif = unpack2(aif);
            float2 zgo = unpack2(ago);

            float ig = 1.f / (1.f + __expf(-zif.x));
            float fg = 1.f / (1.f + __expf(-zif.y));
            float gg = tanhf(zgo.x);
            float og = 1.f / (1.f + __expf(-zgo.y));
            c = fg * c + ig * gg;
            float h = og * tanhf(c);

            __stcg(&hdst[ncol * B_ + bb], h);    // publish h(t+1) via L2
            hout[bb * 4 + nl] = h;

            if (t == T_ - 1) {
                c_fin[bb * H_ + ncol] = c;
                h_fin[bb * H_ + ncol] = h;
            }
        }
        __syncthreads();

        // ---- release h(t+1) to consumers of our slice ----
        if (tid == 0) red_rel_add1(&g_hready[myslice * 32]);

        // ---- coalesced history write (overlaps next step's pipeline) ----
        if (tid < 32) {
            float4 hv4 = ((const float4*)hout)[tid];
            *(float4*)&hist[((size_t)tid * T_ + t) * H_ + blockIdx.x * 4] = hv4;
        }
    }
}

// ---------------- launch ----------------
extern "C" void kernel_launch(void* const* d_in, const int* in_sizes, int n_in,
                              void* d_out, int out_size) {
    const float* x    = (const float*)d_in[0];
    const float* h0   = (const float*)d_in[1];
    const float* c0   = (const float*)d_in[2];
    const float* Wi   = (const float*)d_in[3];
    const float* Wh   = (const float*)d_in[4];
    const float* bias = (const float*)d_in[5];
    float* out = (float*)d_out;

    // 32KB (Wsu) + 64KB (hs) + 16KB (red) + 512B (hout)
    const int rec_smem = 512 * 8 * 8 + 512 * 32 * 4 + 8 * 8 * 32 * 8 + 128 * 4;
    cudaFuncSetAttribute(lstm_rec, cudaFuncAttributeMaxDynamicSharedMemorySize,
                         rec_smem);

    dim3 ggrid(G4H / 64, (B_ * T_) / 64);
    gemm_xwi<<<ggrid, 256>>>(x, Wi, bias, h0);

    lstm_rec<<<NB, NT, rec_smem>>>(c0, Wh, out);
}

// round 8
// speedup vs baseline: 1.3522x; 1.3522x over previous
#include <cuda_runtime.h>
#include <cstdint>

// Problem constants
constexpr int B_  = 32;
constexpr int T_  = 1024;
constexpr int F_  = 512;
constexpr int H_  = 512;
constexpr int G4H = 2048;   // 4*H

#define NB 128   // recurrence blocks (<=148 SMs -> co-resident, grid barrier safe)
#define NT 256   // 8 warps: warp w owns k-slice [64w, 64w+64)
#define KW 64    // k per warp

// ---------------- device scratch ----------------
__device__ float g_z0t[(size_t)T_ * G4H * B_];   // [t][gatecol][b]
__device__ float g_hT[2][H_ * B_];               // ping-pong h, transposed [k][b]
__device__ unsigned g_root;                      // monotonic flat barrier counter

// ---------------- f32x2 + sync helpers ----------------
__device__ __forceinline__ unsigned long long pack2(float x, float y) {
    unsigned long long r;
    asm("mov.b64 %0, {%1, %2};" : "=l"(r) : "f"(x), "f"(y));
    return r;
}
__device__ __forceinline__ unsigned long long fma2(unsigned long long a,
                                                   unsigned long long b,
                                                   unsigned long long c) {
    unsigned long long d;
    asm("fma.rn.f32x2 %0, %1, %2, %3;" : "=l"(d) : "l"(a), "l"(b), "l"(c));
    return d;
}
__device__ __forceinline__ unsigned long long add2(unsigned long long a,
                                                   unsigned long long b) {
    unsigned long long d;
    asm("add.rn.f32x2 %0, %1, %2;" : "=l"(d) : "l"(a), "l"(b));
    return d;
}
__device__ __forceinline__ float2 unpack2(unsigned long long v) {
    float2 f;
    asm("mov.b64 {%0, %1}, %2;" : "=f"(f.x), "=f"(f.y) : "l"(v));
    return f;
}
__device__ __forceinline__ unsigned ld_acq(const unsigned* p) {
    unsigned v;
    asm volatile("ld.acquire.gpu.global.u32 %0, [%1];"
                 : "=r"(v) : "l"(p) : "memory");
    return v;
}
__device__ __forceinline__ void red_rel_add1(unsigned* p) {
    asm volatile("red.release.gpu.global.add.u32 [%0], 1;"
                 :: "l"(p) : "memory");
}

// ---------------- GEMM (f32x2, register double-buffered) + embedded init ----------------
// z0t[t][col][b] = x[b,t,:] @ Wi[:,col] + bias[col]
// M = B*T = 32768, K = 512, N = 2048. 64x64 tile, BK=16, 256 threads,
// smem ping-pong with register prefetch: ONE __syncthreads per k-tile.
__global__ void __launch_bounds__(256) gemm_xwi(const float* __restrict__ x,
                                                const float* __restrict__ Wi,
                                                const float* __restrict__ bias,
                                                const float* __restrict__ h0) {
    __shared__ float As[2][16][64];
    __shared__ float Bs[2][16][64];
    const int tid = threadIdx.x;

    if (blockIdx.x == 0 && blockIdx.y == 0) {
        for (int i = tid; i < H_ * B_; i += 256) {
            int b = i / H_;
            int k = i - b * H_;
            g_hT[0][k * B_ + b] = h0[i];
        }
        if (tid == 0) g_root = 0;
    }

    const int tm = tid >> 4;
    const int tn = tid & 15;
    const int row0 = blockIdx.y * 64;
    const int col0 = blockIdx.x * 64;

    unsigned long long acc[4][2] = {};

    const int ar  = tid >> 2;
    const int akq = (tid & 3) * 4;
    const int br  = tid >> 4;
    const int bnq = (tid & 15) * 4;

    const float* xp = &x[(size_t)(row0 + ar) * F_ + akq];
    const float* wp = &Wi[(size_t)br * G4H + col0 + bnq];

    float4 av = *(const float4*)xp;
    float4 bv = *(const float4*)wp;

    for (int kt = 0; kt < 32; kt++) {
        const int cur = kt & 1;
        As[cur][akq + 0][ar] = av.x;
        As[cur][akq + 1][ar] = av.y;
        As[cur][akq + 2][ar] = av.z;
        As[cur][akq + 3][ar] = av.w;
        *(float4*)&Bs[cur][br][bnq] = bv;
        __syncthreads();
        if (kt < 31) {
            av = *(const float4*)(xp + (kt + 1) * 16);
            bv = *(const float4*)(wp + (size_t)(kt + 1) * 16 * G4H);
        }
#pragma unroll
        for (int k = 0; k < 16; k++) {
            float4 a = *(const float4*)&As[cur][k][tm * 4];
            const unsigned long long* bp =
                (const unsigned long long*)&Bs[cur][k][tn * 4];
            unsigned long long b0 = bp[0], b1 = bp[1];
            unsigned long long a0 = pack2(a.x, a.x);
            unsigned long long a1 = pack2(a.y, a.y);
            unsigned long long a2 = pack2(a.z, a.z);
            unsigned long long a3 = pack2(a.w, a.w);
            acc[0][0] = fma2(a0, b0, acc[0][0]); acc[0][1] = fma2(a0, b1, acc[0][1]);
            acc[1][0] = fma2(a1, b0, acc[1][0]); acc[1][1] = fma2(a1, b1, acc[1][1]);
            acc[2][0] = fma2(a2, b0, acc[2][0]); acc[2][1] = fma2(a2, b1, acc[2][1]);
            acc[3][0] = fma2(a3, b0, acc[3][0]); acc[3][1] = fma2(a3, b1, acc[3][1]);
        }
    }

#pragma unroll
    for (int i = 0; i < 4; i++) {
        int r  = row0 + tm * 4 + i;
        int t  = r & (T_ - 1);
        int bb = r >> 10;
#pragma unroll
        for (int j = 0; j < 2; j++) {
            float2 v = unpack2(acc[i][j]);
            int c0c = col0 + tn * 4 + j * 2;
            g_z0t[((size_t)t * G4H + c0c + 0) * B_ + bb] = v.x + bias[c0c + 0];
            g_z0t[((size_t)t * G4H + c0c + 1) * B_ + bb] = v.y + bias[c0c + 1];
        }
    }
}

// ---------------- recurrence (round-6 structure; flat barrier; MLP-16 stage) ----------------
// Block bx owns h columns [bx*4, bx*4+4).
// Compute mapping: warp w = tid>>5 owns k in [64w,64w+64); lane = batch b.
// Epilogue mapping (tid<128): warp = nl (column), lane = b.
// Dynamic smem:
//   Wsu[512*8] u64  32KB : per k, [(wi,wf),(wg,wo)] x 4 cols
//   hs [512*32] f32 64KB : h state [k][b]
//   red[8*8*32] u64 16KB : red[j][w][b] split-k partials
//   hout[32*4]  f32 .5KB : h transpose buffer for coalesced hist store
__global__ void __launch_bounds__(NT, 1) lstm_rec(const float* __restrict__ c0,
                                                  const float* __restrict__ Wh,
                                                  float* __restrict__ out) {
    extern __shared__ unsigned char dsm[];
    unsigned long long* Wsu = (unsigned long long*)dsm;          // [k*8 + nl*2]
    float* hs = (float*)(Wsu + 512 * 8);                         // [k*32 + b]
    unsigned long long* red = (unsigned long long*)(hs + 512*32);// [j*256+w*32+b]
    float* hout = (float*)(red + 8 * 8 * 32);                    // [b*4 + nl]

    const int tid = threadIdx.x;
    const int w   = tid >> 5;
    const int b   = tid & 31;

    // Stage Wh slice once: (wi,wf),(wg,wo) pairs per (k, col nl).
    for (int idx = tid; idx < H_ * 4; idx += NT) {
        int k  = idx >> 2;
        int n2 = idx & 3;
        int cb = blockIdx.x * 4 + n2;
        float wi = Wh[(size_t)k * G4H + 0 * H_ + cb];
        float wf = Wh[(size_t)k * G4H + 1 * H_ + cb];
        float wg = Wh[(size_t)k * G4H + 2 * H_ + cb];
        float wo = Wh[(size_t)k * G4H + 3 * H_ + cb];
        Wsu[k * 8 + n2 * 2 + 0] = pack2(wi, wf);
        Wsu[k * 8 + n2 * 2 + 1] = pack2(wg, wo);
    }

    // Epilogue-mapped state (tid < 128): nl = tid>>5, bb = tid&31.
    const int nl = tid >> 5;
    const int bb = tid & 31;
    const int ncol = blockIdx.x * 4 + nl;
    float c = (tid < 128) ? c0[(size_t)bb * H_ + ncol] : 0.f;

    float* c_fin = out;
    float* h_fin = out + B_ * H_;
    float* hist  = out + 2 * B_ * H_;            // [b][t][h]

    __syncthreads();

    for (int t = 0; t < T_; t++) {
        const float4* __restrict__ hsrc4 = (const float4*)g_hT[t & 1];
        float* hdst = g_hT[(t + 1) & 1];
        float4* hsf4 = (float4*)hs;

        // ---- z prefetch (epilogue threads; overlaps stage + compute) ----
        float z0 = 0.f, z1 = 0.f, z2 = 0.f, z3 = 0.f;
        if (tid < 128) {
            size_t zb = ((size_t)t * G4H + ncol) * B_ + bb;
            z0 = __ldcs(&g_z0t[zb + (size_t)0 * H_ * B_]);
            z1 = __ldcs(&g_z0t[zb + (size_t)1 * H_ * B_]);
            z2 = __ldcs(&g_z0t[zb + (size_t)2 * H_ * B_]);
            z3 = __ldcs(&g_z0t[zb + (size_t)3 * H_ * B_]);
        }

        // ---- warp-local stage, MLP=16: all 16 LDGs in flight, then 16 STS ----
        {
            const int base = w * 512;
            float4 r[16];
#pragma unroll
            for (int i = 0; i < 16; i++)
                r[i] = __ldcg(&hsrc4[base + i * 32 + b]);
#pragma unroll
            for (int i = 0; i < 16; i++)
                hsf4[base + i * 32 + b] = r[i];
        }
        __syncwarp();

        // ---- compute: 64 k, 16 FMA2s each (4 cols x 4 gates), h read ONCE ----
        unsigned long long a0 = 0, a1 = 0, a2 = 0, a3 = 0;
        unsigned long long a4 = 0, a5 = 0, a6 = 0, a7 = 0;
        {
            const float* hp = hs + (size_t)w * KW * 32 + b;
            const ulonglong2* wp = (const ulonglong2*)(Wsu + (size_t)w * KW * 8);
#pragma unroll 4
            for (int kk = 0; kk < KW; kk++) {
                float hv = hp[kk * 32];
                unsigned long long hh = pack2(hv, hv);
                ulonglong2 w01 = wp[kk * 4 + 0];
                ulonglong2 w23 = wp[kk * 4 + 1];
                ulonglong2 w45 = wp[kk * 4 + 2];
                ulonglong2 w67 = wp[kk * 4 + 3];
                a0 = fma2(hh, w01.x, a0); a1 = fma2(hh, w01.y, a1);
                a2 = fma2(hh, w23.x, a2); a3 = fma2(hh, w23.y, a3);
                a4 = fma2(hh, w45.x, a4); a5 = fma2(hh, w45.y, a5);
                a6 = fma2(hh, w67.x, a6); a7 = fma2(hh, w67.y, a7);
            }
        }

        // ---- publish partials: red[j][w][b] (conflict-free) ----
        red[0 * 256 + w * 32 + b] = a0;
        red[1 * 256 + w * 32 + b] = a1;
        red[2 * 256 + w * 32 + b] = a2;
        red[3 * 256 + w * 32 + b] = a3;
        red[4 * 256 + w * 32 + b] = a4;
        red[5 * 256 + w * 32 + b] = a5;
        red[6 * 256 + w * 32 + b] = a6;
        red[7 * 256 + w * 32 + b] = a7;
        __syncthreads();

        // ---- reduce + gates (epilogue threads, col nl / batch bb) ----
        if (tid < 128) {
            const unsigned long long* rif = red + (nl * 2 + 0) * 256 + bb;
            const unsigned long long* rgo = red + (nl * 2 + 1) * 256 + bb;
            unsigned long long aif = pack2(z0, z1);
            unsigned long long ago = pack2(z2, z3);
#pragma unroll
            for (int ww = 0; ww < 8; ww++) {
                aif = add2(aif, rif[ww * 32]);
                ago = add2(ago, rgo[ww * 32]);
            }
            float2 zif = unpack2(aif);
            float2 zgo = unpack2(ago);

            float ig = 1.f / (1.f + __expf(-zif.x));
            float fg = 1.f / (1.f + __expf(-zif.y));
            float gg = tanhf(zgo.x);
            float og = 1.f / (1.f + __expf(-zgo.y));
            c = fg * c + ig * gg;
            float h = og * tanhf(c);

            __stcg(&hdst[ncol * B_ + bb], h);    // publish via L2 (coalesced)
            hout[bb * 4 + nl] = h;

            if (t == T_ - 1) {
                c_fin[bb * H_ + ncol] = c;
                h_fin[bb * H_ + ncol] = h;
            }
        }
        __syncthreads();

        // ---- coalesced history write: one STG.128 per batch row ----
        if (tid < 32) {
            float4 hv4 = ((const float4*)hout)[tid];
            *(float4*)&hist[((size_t)tid * T_ + t) * H_ + blockIdx.x * 4] = hv4;
        }

        // ---- flat monotonic grid barrier (release arrive + acquire poll) ----
        // release-add orders this block's h publish (validated pattern, R7);
        // counter reaching 128*(t+1) IS the release — no separate flag store.
        if (tid == 0) {
            red_rel_add1(&g_root);
            unsigned target = 128u * (unsigned)(t + 1);
            while (ld_acq(&g_root) < target) { }
        }
        __syncthreads();
        // no consumer threadfence: cross-step reads bypass L1 (.cg) and the
        // acquire-load synchronizes with producers' release-adds.
    }
}

// ---------------- launch ----------------
extern "C" void kernel_launch(void* const* d_in, const int* in_sizes, int n_in,
                              void* d_out, int out_size) {
    const float* x    = (const float*)d_in[0];
    const float* h0   = (const float*)d_in[1];
    const float* c0   = (const float*)d_in[2];
    const float* Wi   = (const float*)d_in[3];
    const float* Wh   = (const float*)d_in[4];
    const float* bias = (const float*)d_in[5];
    float* out = (float*)d_out;

    // 32KB (Wsu) + 64KB (hs) + 16KB (red) + 512B (hout)
    const int rec_smem = 512 * 8 * 8 + 512 * 32 * 4 + 8 * 8 * 32 * 8 + 128 * 4;
    cudaFuncSetAttribute(lstm_rec, cudaFuncAttributeMaxDynamicSharedMemorySize,
                         rec_smem);

    dim3 ggrid(G4H / 64, (B_ * T_) / 64);
    gemm_xwi<<<ggrid, 256>>>(x, Wi, bias, h0);

    lstm_rec<<<NB, NT, rec_smem>>>(c0, Wh, out);
}

// round 9
// speedup vs baseline: 1.3687x; 1.0122x over previous
#include <cuda_runtime.h>
#include <cstdint>

// Problem constants
constexpr int B_  = 32;
constexpr int T_  = 1024;
constexpr int F_  = 512;
constexpr int H_  = 512;
constexpr int G4H = 2048;   // 4*H

#define NB 128   // recurrence blocks (<=148 SMs -> co-resident, grid barrier safe)
#define NT 256   // 8 warps: warp w owns k-slice [64w, 64w+64)
#define KW 64    // k per warp

// ---------------- device scratch ----------------
__device__ float g_z0t[(size_t)T_ * G4H * B_];   // [t][gatecol][b]
__device__ float g_hT[2][H_ * B_];               // ping-pong h, transposed [k][b]
__device__ unsigned g_root;                      // monotonic flat barrier counter

// ---------------- f32x2 + sync helpers ----------------
__device__ __forceinline__ unsigned long long pack2(float x, float y) {
    unsigned long long r;
    asm("mov.b64 %0, {%1, %2};" : "=l"(r) : "f"(x), "f"(y));
    return r;
}
__device__ __forceinline__ unsigned long long fma2(unsigned long long a,
                                                   unsigned long long b,
                                                   unsigned long long c) {
    unsigned long long d;
    asm("fma.rn.f32x2 %0, %1, %2, %3;" : "=l"(d) : "l"(a), "l"(b), "l"(c));
    return d;
}
__device__ __forceinline__ unsigned long long add2(unsigned long long a,
                                                   unsigned long long b) {
    unsigned long long d;
    asm("add.rn.f32x2 %0, %1, %2;" : "=l"(d) : "l"(a), "l"(b));
    return d;
}
__device__ __forceinline__ float2 unpack2(unsigned long long v) {
    float2 f;
    asm("mov.b64 {%0, %1}, %2;" : "=f"(f.x), "=f"(f.y) : "l"(v));
    return f;
}
__device__ __forceinline__ unsigned ld_acq(const unsigned* p) {
    unsigned v;
    asm volatile("ld.acquire.gpu.global.u32 %0, [%1];"
                 : "=r"(v) : "l"(p) : "memory");
    return v;
}
__device__ __forceinline__ void red_rel_add1(unsigned* p) {
    asm volatile("red.release.gpu.global.add.u32 [%0], 1;"
                 :: "l"(p) : "memory");
}
// Fast MUFU-path activations (same accuracy class as __expf sigmoid).
__device__ __forceinline__ float sigf(float x) {
    return 1.f / (1.f + __expf(-x));
}
__device__ __forceinline__ float tanh_fast(float x) {
    return 2.f / (1.f + __expf(-2.f * x)) - 1.f;
}

// ---------------- GEMM (f32x2, register double-buffered) + embedded init ----------------
// z0t[t][col][b] = x[b,t,:] @ Wi[:,col] + bias[col]
// M = B*T = 32768, K = 512, N = 2048. 64x64 tile, BK=16, 256 threads,
// smem ping-pong with register prefetch: ONE __syncthreads per k-tile.
__global__ void __launch_bounds__(256) gemm_xwi(const float* __restrict__ x,
                                                const float* __restrict__ Wi,
                                                const float* __restrict__ bias,
                                                const float* __restrict__ h0) {
    __shared__ float As[2][16][64];
    __shared__ float Bs[2][16][64];
    const int tid = threadIdx.x;

    if (blockIdx.x == 0 && blockIdx.y == 0) {
        for (int i = tid; i < H_ * B_; i += 256) {
            int b = i / H_;
            int k = i - b * H_;
            g_hT[0][k * B_ + b] = h0[i];
        }
        if (tid == 0) g_root = 0;
    }

    const int tm = tid >> 4;
    const int tn = tid & 15;
    const int row0 = blockIdx.y * 64;
    const int col0 = blockIdx.x * 64;

    unsigned long long acc[4][2] = {};

    const int ar  = tid >> 2;
    const int akq = (tid & 3) * 4;
    const int br  = tid >> 4;
    const int bnq = (tid & 15) * 4;

    const float* xp = &x[(size_t)(row0 + ar) * F_ + akq];
    const float* wp = &Wi[(size_t)br * G4H + col0 + bnq];

    float4 av = *(const float4*)xp;
    float4 bv = *(const float4*)wp;

    for (int kt = 0; kt < 32; kt++) {
        const int cur = kt & 1;
        As[cur][akq + 0][ar] = av.x;
        As[cur][akq + 1][ar] = av.y;
        As[cur][akq + 2][ar] = av.z;
        As[cur][akq + 3][ar] = av.w;
        *(float4*)&Bs[cur][br][bnq] = bv;
        __syncthreads();
        if (kt < 31) {
            av = *(const float4*)(xp + (kt + 1) * 16);
            bv = *(const float4*)(wp + (size_t)(kt + 1) * 16 * G4H);
        }
#pragma unroll
        for (int k = 0; k < 16; k++) {
            float4 a = *(const float4*)&As[cur][k][tm * 4];
            const unsigned long long* bp =
                (const unsigned long long*)&Bs[cur][k][tn * 4];
            unsigned long long b0 = bp[0], b1 = bp[1];
            unsigned long long a0 = pack2(a.x, a.x);
            unsigned long long a1 = pack2(a.y, a.y);
            unsigned long long a2 = pack2(a.z, a.z);
            unsigned long long a3 = pack2(a.w, a.w);
            acc[0][0] = fma2(a0, b0, acc[0][0]); acc[0][1] = fma2(a0, b1, acc[0][1]);
            acc[1][0] = fma2(a1, b0, acc[1][0]); acc[1][1] = fma2(a1, b1, acc[1][1]);
            acc[2][0] = fma2(a2, b0, acc[2][0]); acc[2][1] = fma2(a2, b1, acc[2][1]);
            acc[3][0] = fma2(a3, b0, acc[3][0]); acc[3][1] = fma2(a3, b1, acc[3][1]);
        }
    }

#pragma unroll
    for (int i = 0; i < 4; i++) {
        int r  = row0 + tm * 4 + i;
        int t  = r & (T_ - 1);
        int bb = r >> 10;
#pragma unroll
        for (int j = 0; j < 2; j++) {
            float2 v = unpack2(acc[i][j]);
            int c0c = col0 + tn * 4 + j * 2;
            g_z0t[((size_t)t * G4H + c0c + 0) * B_ + bb] = v.x + bias[c0c + 0];
            g_z0t[((size_t)t * G4H + c0c + 1) * B_ + bb] = v.y + bias[c0c + 1];
        }
    }
}

// ---------------- recurrence ----------------
// Block bx owns h columns [bx*4, bx*4+4).
// Compute mapping: warp w = tid>>5 owns k in [64w,64w+64); lane = batch b.
// Epilogue mapping (tid<128): warp = nl (column), lane = b.
// Critical path per step: poll-detect -> stage(A) -> compute(A/B overlap) ->
// reduce -> fast gates -> publish -> arrive. hist write + z prefetch live
// between arrive and the next poll (off the critical path).
__global__ void __launch_bounds__(NT, 1) lstm_rec(const float* __restrict__ c0,
                                                  const float* __restrict__ Wh,
                                                  float* __restrict__ out) {
    extern __shared__ unsigned char dsm[];
    unsigned long long* Wsu = (unsigned long long*)dsm;          // [k*8 + nl*2]
    float* hs = (float*)(Wsu + 512 * 8);                         // [k*32 + b]
    unsigned long long* red = (unsigned long long*)(hs + 512*32);// [j*256+w*32+b]
    float* hout = (float*)(red + 8 * 8 * 32);                    // [b*4 + nl]

    const int tid = threadIdx.x;
    const int w   = tid >> 5;
    const int b   = tid & 31;

    // Stage Wh slice once: (wi,wf),(wg,wo) pairs per (k, col nl).
    for (int idx = tid; idx < H_ * 4; idx += NT) {
        int k  = idx >> 2;
        int n2 = idx & 3;
        int cb = blockIdx.x * 4 + n2;
        float wi = Wh[(size_t)k * G4H + 0 * H_ + cb];
        float wf = Wh[(size_t)k * G4H + 1 * H_ + cb];
        float wg = Wh[(size_t)k * G4H + 2 * H_ + cb];
        float wo = Wh[(size_t)k * G4H + 3 * H_ + cb];
        Wsu[k * 8 + n2 * 2 + 0] = pack2(wi, wf);
        Wsu[k * 8 + n2 * 2 + 1] = pack2(wg, wo);
    }

    // Epilogue-mapped state (tid < 128): nl = tid>>5, bb = tid&31.
    const int nl = tid >> 5;
    const int bb = tid & 31;
    const int ncol = blockIdx.x * 4 + nl;
    float c = (tid < 128) ? c0[(size_t)bb * H_ + ncol] : 0.f;

    float* c_fin = out;
    float* h_fin = out + B_ * H_;
    float* hist  = out + 2 * B_ * H_;            // [b][t][h]

    __syncthreads();

    // z prefetch for t = 0 (before any waiting).
    float z0 = 0.f, z1 = 0.f, z2 = 0.f, z3 = 0.f;
    if (tid < 128) {
        size_t zb = ((size_t)0 * G4H + ncol) * B_ + bb;
        z0 = __ldcs(&g_z0t[zb + (size_t)0 * H_ * B_]);
        z1 = __ldcs(&g_z0t[zb + (size_t)1 * H_ * B_]);
        z2 = __ldcs(&g_z0t[zb + (size_t)2 * H_ * B_]);
        z3 = __ldcs(&g_z0t[zb + (size_t)3 * H_ * B_]);
    }

    for (int t = 0; t < T_; t++) {
        const float4* __restrict__ hsrc4 = (const float4*)g_hT[t & 1];
        float* hdst = g_hT[(t + 1) & 1];
        float4* hsf4 = (float4*)hs;

        // ---- wait for h(t): all 128 blocks arrived t times ----
        if (t > 0 && tid == 0) {
            unsigned target = 128u * (unsigned)t;
            while (ld_acq(&g_root) < target) { }
        }
        __syncthreads();

        // ---- stage: 16 LDGs in flight; STS+compute A overlaps B's loads ----
        const int base = w * 512;
        float4 r[16];
#pragma unroll
        for (int i = 0; i < 16; i++)
            r[i] = __ldcg(&hsrc4[base + i * 32 + b]);
#pragma unroll
        for (int i = 0; i < 8; i++)
            hsf4[base + i * 32 + b] = r[i];
        __syncwarp();

        unsigned long long a0 = 0, a1 = 0, a2 = 0, a3 = 0;
        unsigned long long a4 = 0, a5 = 0, a6 = 0, a7 = 0;
        const float* hp = hs + (size_t)w * KW * 32 + b;
        const ulonglong2* wp = (const ulonglong2*)(Wsu + (size_t)w * KW * 8);

#pragma unroll 4
        for (int kk = 0; kk < 32; kk++) {           // phase A: k 0..31
            float hv = hp[kk * 32];
            unsigned long long hh = pack2(hv, hv);
            ulonglong2 w01 = wp[kk * 4 + 0];
            ulonglong2 w23 = wp[kk * 4 + 1];
            ulonglong2 w45 = wp[kk * 4 + 2];
            ulonglong2 w67 = wp[kk * 4 + 3];
            a0 = fma2(hh, w01.x, a0); a1 = fma2(hh, w01.y, a1);
            a2 = fma2(hh, w23.x, a2); a3 = fma2(hh, w23.y, a3);
            a4 = fma2(hh, w45.x, a4); a5 = fma2(hh, w45.y, a5);
            a6 = fma2(hh, w67.x, a6); a7 = fma2(hh, w67.y, a7);
        }

#pragma unroll
        for (int i = 8; i < 16; i++)
            hsf4[base + i * 32 + b] = r[i];
        __syncwarp();

#pragma unroll 4
        for (int kk = 32; kk < 64; kk++) {          // phase B: k 32..63
            float hv = hp[kk * 32];
            unsigned long long hh = pack2(hv, hv);
            ulonglong2 w01 = wp[kk * 4 + 0];
            ulonglong2 w23 = wp[kk * 4 + 1];
            ulonglong2 w45 = wp[kk * 4 + 2];
            ulonglong2 w67 = wp[kk * 4 + 3];
            a0 = fma2(hh, w01.x, a0); a1 = fma2(hh, w01.y, a1);
            a2 = fma2(hh, w23.x, a2); a3 = fma2(hh, w23.y, a3);
            a4 = fma2(hh, w45.x, a4); a5 = fma2(hh, w45.y, a5);
            a6 = fma2(hh, w67.x, a6); a7 = fma2(hh, w67.y, a7);
        }

        // ---- publish partials: red[j][w][b] (conflict-free) ----
        red[0 * 256 + w * 32 + b] = a0;
        red[1 * 256 + w * 32 + b] = a1;
        red[2 * 256 + w * 32 + b] = a2;
        red[3 * 256 + w * 32 + b] = a3;
        red[4 * 256 + w * 32 + b] = a4;
        red[5 * 256 + w * 32 + b] = a5;
        red[6 * 256 + w * 32 + b] = a6;
        red[7 * 256 + w * 32 + b] = a7;
        __syncthreads();

        // ---- reduce + fast gates (epilogue threads, col nl / batch bb) ----
        float h = 0.f;
        if (tid < 128) {
            const unsigned long long* rif = red + (nl * 2 + 0) * 256 + bb;
            const unsigned long long* rgo = red + (nl * 2 + 1) * 256 + bb;
            unsigned long long aif = pack2(z0, z1);
            unsigned long long ago = pack2(z2, z3);
#pragma unroll
            for (int ww = 0; ww < 8; ww++) {
                aif = add2(aif, rif[ww * 32]);
                ago = add2(ago, rgo[ww * 32]);
            }
            float2 zif = unpack2(aif);
            float2 zgo = unpack2(ago);

            float ig = sigf(zif.x);
            float fg = sigf(zif.y);
            float gg = tanh_fast(zgo.x);
            float og = sigf(zgo.y);
            c = fg * c + ig * gg;
            h = og * tanh_fast(c);

            __stcg(&hdst[ncol * B_ + bb], h);    // publish via L2 (coalesced)
            hout[bb * 4 + nl] = h;
        }
        __syncthreads();

        // ---- arrive ASAP: h(t+1) of this block is published ----
        if (tid == 0) red_rel_add1(&g_root);

        // ---- off-critical-path tail: hist write + next z prefetch ----
        if (tid < 32) {
            float4 hv4 = ((const float4*)hout)[tid];
            *(float4*)&hist[((size_t)tid * T_ + t) * H_ + blockIdx.x * 4] = hv4;
        }
        if (tid < 128) {
            if (t == T_ - 1) {
                c_fin[bb * H_ + ncol] = c;
                h_fin[bb * H_ + ncol] = h;
            } else {
                size_t zb = ((size_t)(t + 1) * G4H + ncol) * B_ + bb;
                z0 = __ldcs(&g_z0t[zb + (size_t)0 * H_ * B_]);
                z1 = __ldcs(&g_z0t[zb + (size_t)1 * H_ * B_]);
                z2 = __ldcs(&g_z0t[zb + (size_t)2 * H_ * B_]);
                z3 = __ldcs(&g_z0t[zb + (size_t)3 * H_ * B_]);
            }
        }
    }
}

// ---------------- launch ----------------
extern "C" void kernel_launch(void* const* d_in, const int* in_sizes, int n_in,
                              void* d_out, int out_size) {
    const float* x    = (const float*)d_in[0];
    const float* h0   = (const float*)d_in[1];
    const float* c0   = (const float*)d_in[2];
    const float* Wi   = (const float*)d_in[3];
    const float* Wh   = (const float*)d_in[4];
    const float* bias = (const float*)d_in[5];
    float* out = (float*)d_out;

    // 32KB (Wsu) + 64KB (hs) + 16KB (red) + 512B (hout)
    const int rec_smem = 512 * 8 * 8 + 512 * 32 * 4 + 8 * 8 * 32 * 8 + 128 * 4;
    cudaFuncSetAttribute(lstm_rec, cudaFuncAttributeMaxDynamicSharedMemorySize,
                         rec_smem);

    dim3 ggrid(G4H / 64, (B_ * T_) / 64);
    gemm_xwi<<<ggrid, 256>>>(x, Wi, bias, h0);

    lstm_rec<<<NB, NT, rec_smem>>>(c0, Wh, out);
}